// round 14
// baseline (speedup 1.0000x reference)
#include <cuda_runtime.h>
#include <cuda_fp16.h>
#include <cstdint>
#include <cstddef>

#define NPC  16            // nodes per CTA
#define TPB  256
#define KNB  32

#define ASTRIDE 72         // stage row stride fp32 / W1 fp16

// ---- dynamic SMEM layout (bytes) ----
#define SM_BIAS   0                       // b1 f32[64]
#define SM_B2S    256                     // b2 f32[64]
#define SM_INV    512                     // inv-norm f32[16]
#define SM_BW     3072                    // W1 fp16: [64][72] (9216B)
#define SM_NBPART 12288                   // f32[16 nodes][2 mt][66] (8448B); reused as ynorm [16][68]
#define SM_HSELF  20736                   // f32[16][66] (4224B)
#define SM_AGGR   24960                   // f32[16][66] (4224B)
#define SM_STG0   29184                   // fp32 stage buf0: [128][72] (36864B)
#define SM_STG1   66048                   // fp32 stage buf1 (36864B); reused for E1F/W2F
#define SM_TOTAL  102912                  // 2 CTAs/SM

#define SM_E1F    SM_STG1                 // E1 fp32 [64][68] (17408B)
#define SM_W2F    (SM_STG1 + 17408)       // W2 fp32 [64][68] (17408B)
#define SM_YN     SM_NBPART               // ynorm f32 [16][68]

__device__ int g_max_bits[64];            // zero at load; reset_kernel re-zeros each call

__device__ __forceinline__ void mma16816h(float* d,
                                          uint32_t a0, uint32_t a1, uint32_t a2, uint32_t a3,
                                          uint32_t b0, uint32_t b1) {
    asm volatile(
        "mma.sync.aligned.m16n8k16.row.col.f32.f16.f16.f32 "
        "{%0,%1,%2,%3}, {%4,%5,%6,%7}, {%8,%9}, {%0,%1,%2,%3};"
        : "+f"(d[0]), "+f"(d[1]), "+f"(d[2]), "+f"(d[3])
        : "r"(a0), "r"(a1), "r"(a2), "r"(a3), "r"(b0), "r"(b1));
}

__device__ __forceinline__ void ldmatrix_x4(uint32_t& r0, uint32_t& r1,
                                            uint32_t& r2, uint32_t& r3, uint32_t addr) {
    asm volatile("ldmatrix.sync.aligned.m8n8.x4.shared.b16 {%0,%1,%2,%3}, [%4];"
                 : "=r"(r0), "=r"(r1), "=r"(r2), "=r"(r3) : "r"(addr));
}

__device__ __forceinline__ void cp_async16(void* dst, const void* src) {
    unsigned s = (unsigned)__cvta_generic_to_shared(dst);
    asm volatile("cp.async.cg.shared.global [%0], [%1], 16;" :: "r"(s), "l"(src) : "memory");
}
__device__ __forceinline__ void cp_commit() {
    asm volatile("cp.async.commit_group;" ::: "memory");
}

__device__ __forceinline__ uint32_t h2_bits(__half2 h) {
    return *reinterpret_cast<uint32_t*>(&h);
}
__device__ __forceinline__ uint32_t cvt_h2(float2 v) {
    return h2_bits(__float22half2_rn(v));
}
// split fp32 pair into fp16x2 hi + residual lo (epilogue accuracy path only)
__device__ __forceinline__ void split2h(float2 v, uint32_t& hi, uint32_t& lo) {
    __half2 h = __float22half2_rn(v);
    float2 hf = __half22float2(h);
    __half2 l = __float22half2_rn(make_float2(v.x - hf.x, v.y - hf.y));
    hi = h2_bits(h);
    lo = h2_bits(l);
}

extern "C" __global__ void __launch_bounds__(TPB, 2)
stage1_kernel(const float* __restrict__ xs, const float* __restrict__ xnb,
              const float* __restrict__ W1, const float* __restrict__ b1,
              const float* __restrict__ E1, const float* __restrict__ W2,
              const float* __restrict__ b2, int n)
{
    extern __shared__ char smem[];
    const int tid = threadIdx.x, wid = tid >> 5, lane = tid & 31;
    const int t4 = lane >> 2, tm4 = lane & 3;
    const int base = blockIdx.x * NPC;

    float* sB     = (float*)(smem + SM_BIAS);
    float* sB2    = (float*)(smem + SM_B2S);
    float* sInv   = (float*)(smem + SM_INV);
    float* nbpart = (float*)(smem + SM_NBPART);
    float* hself  = (float*)(smem + SM_HSELF);
    float* aggrb  = (float*)(smem + SM_AGGR);
    float* ynorm  = (float*)(smem + SM_YN);
    const float* E1F = (const float*)(smem + SM_E1F);
    const float* W2F = (const float*)(smem + SM_W2F);

    if (tid < 64) sB[tid] = b1[tid];
    else if (tid < 128) sB2[tid - 64] = b2[tid - 64];

    // ---- stage W1 fp16: [o][k], stride 72 ----
    #pragma unroll
    for (int j = 0; j < 4; ++j) {
        int idx = tid + j * TPB;              // 0..1023
        int o = idx >> 4, c4 = idx & 15;
        float4 v = __ldg((const float4*)(W1 + o * 64 + c4 * 4));
        *(uint2*)(smem + SM_BW + (o * ASTRIDE + c4 * 4) * 2) =
            make_uint2(cvt_h2(make_float2(v.x, v.y)), cvt_h2(make_float2(v.z, v.w)));
    }

    // per-lane ldmatrix base addresses for B fragment pairs (pair p -> nt=2p, 2p+1)
    // matrix m = lane>>3: m>>1 selects nt within pair, m&1 selects k-half (col 0/8)
    const uint32_t bw_u32 = (uint32_t)__cvta_generic_to_shared(smem + SM_BW);
    const int nt_off = (lane >> 4) & 1, colh = (lane >> 3) & 1, r8 = lane & 7;
    uint32_t bbase[4];
    #pragma unroll
    for (int p = 0; p < 4; ++p)
        bbase[p] = bw_u32 + ((((2 * p + nt_off) * 8 + r8) * ASTRIDE) + colh * 8) * 2;

    // stage fp32 rows: t<4 -> 128 neighbor rows (nodes t*4..t*4+3); t==4 -> 16 self rows
    auto fillStage = [&](int t, char* buf) {
        if (t < 4) {
            #pragma unroll
            for (int j = 0; j < 8; ++j) {
                int idx = tid + j * TPB;      // 0..2047
                int row = idx >> 4, c4 = idx & 15;
                int gn = base + t * 4 + (row >> 5); if (gn >= n) gn = n - 1;
                cp_async16((float*)buf + row * ASTRIDE + c4 * 4,
                           xnb + ((size_t)gn * KNB + (row & 31)) * 64 + c4 * 4);
            }
        } else {
            int row = tid >> 4, c4 = tid & 15;
            int gn = base + row; if (gn >= n) gn = n - 1;
            cp_async16((float*)buf + row * ASTRIDE + c4 * 4,
                       xs + (size_t)gn * 64 + c4 * 4);
        }
        cp_commit();
    };

    const __half* Bw = (const __half*)(smem + SM_BW);

    fillStage(0, smem + SM_STG0);

    for (int t = 0; t <= 4; ++t) {
        if (t < 4) {
            fillStage(t + 1, smem + (((t + 1) & 1) ? SM_STG1 : SM_STG0));
            asm volatile("cp.async.wait_group 1;" ::: "memory");
        } else {
            asm volatile("cp.async.wait_group 0;" ::: "memory");
        }
        __syncthreads();     // stage t ready

        if (t == 4) {
            // prefetch E1/W2 fp32 into padded [64][68] (STG1 free now); overlaps self compute
            #pragma unroll
            for (int j = 0; j < 4; ++j) {
                int idx = tid + j * TPB;      // 0..1023
                int row = idx >> 4, c4 = idx & 15;
                cp_async16((float*)(smem + SM_E1F) + row * 68 + c4 * 4, E1 + row * 64 + c4 * 4);
            }
            #pragma unroll
            for (int j = 0; j < 4; ++j) {
                int idx = tid + j * TPB;
                int row = idx >> 4, c4 = idx & 15;
                cp_async16((float*)(smem + SM_W2F) + row * 68 + c4 * 4, W2 + row * 64 + c4 * 4);
            }
            cp_commit();
        }

        const float* stg = (const float*)(smem + ((t & 1) ? SM_STG1 : SM_STG0));

        if (t < 4) {
            const int ln = wid >> 1, mt = wid & 1;
            const int r0 = ln * 32 + mt * 16 + t4;

            float acc[8][4];
            #pragma unroll
            for (int nt = 0; nt < 8; ++nt)
                #pragma unroll
                for (int q = 0; q < 4; ++q) acc[nt][q] = 0.f;

            #pragma unroll
            for (int k0 = 0; k0 < 4; ++k0) {
                const int cb = 16 * k0 + 2 * tm4;
                // A fragments: fp32 pairs -> single-rounded fp16x2
                uint32_t ah[4];
                {
                    const float* ap = stg + r0 * ASTRIDE + cb;
                    ah[0] = cvt_h2(*(const float2*)ap);
                    ah[1] = cvt_h2(*(const float2*)(ap + 8 * ASTRIDE));
                    ah[2] = cvt_h2(*(const float2*)(ap + 8));
                    ah[3] = cvt_h2(*(const float2*)(ap + 8 * ASTRIDE + 8));
                }
                // B fragments for all 8 n-tiles via 4x ldmatrix.x4
                uint32_t bv0[8], bv1[8];
                #pragma unroll
                for (int p = 0; p < 4; ++p)
                    ldmatrix_x4(bv0[2 * p], bv1[2 * p], bv0[2 * p + 1], bv1[2 * p + 1],
                                bbase[p] + 32 * k0);
                #pragma unroll
                for (int nt = 0; nt < 8; ++nt)
                    mma16816h(acc[nt], ah[0], ah[1], ah[2], ah[3], bv0[nt], bv1[nt]);
            }

            const int node = t * 4 + ln;
            float* dst = nbpart + (node * 2 + mt) * 66;
            #pragma unroll
            for (int nt = 0; nt < 8; ++nt) {
                float v0 = fmaxf(acc[nt][0], acc[nt][2]);
                float v1 = fmaxf(acc[nt][1], acc[nt][3]);
                #pragma unroll
                for (int off = 4; off <= 16; off <<= 1) {
                    v0 = fmaxf(v0, __shfl_xor_sync(0xffffffffu, v0, off));
                    v1 = fmaxf(v1, __shfl_xor_sync(0xffffffffu, v1, off));
                }
                if (lane < 4) {
                    dst[nt * 8 + 2 * lane]     = v0;
                    dst[nt * 8 + 2 * lane + 1] = v1;
                }
            }
        } else {
            // self tile: 16 rows x 64 cols; warp w computes n-tile nt=w
            float acc[4] = {0.f, 0.f, 0.f, 0.f};
            #pragma unroll
            for (int k0 = 0; k0 < 4; ++k0) {
                const int cb = 16 * k0 + 2 * tm4;
                uint32_t ah[4];
                {
                    const float* ap = stg + t4 * ASTRIDE + cb;
                    ah[0] = cvt_h2(*(const float2*)ap);
                    ah[1] = cvt_h2(*(const float2*)(ap + 8 * ASTRIDE));
                    ah[2] = cvt_h2(*(const float2*)(ap + 8));
                    ah[3] = cvt_h2(*(const float2*)(ap + 8 * ASTRIDE + 8));
                }
                const __half* bp = Bw + (wid * 8 + t4) * ASTRIDE + cb;
                uint32_t b0 = *(const uint32_t*)bp;
                uint32_t b1 = *(const uint32_t*)(bp + 8);
                mma16816h(acc, ah[0], ah[1], ah[2], ah[3], b0, b1);
            }
            const int c = wid * 8 + 2 * tm4;
            hself[t4 * 66 + c]           = acc[0];
            hself[t4 * 66 + c + 1]       = acc[1];
            hself[(t4 + 8) * 66 + c]     = acc[2];
            hself[(t4 + 8) * 66 + c + 1] = acc[3];
        }
        __syncthreads();
    }

    // ---- combine: aggr = relu(max(nb_mt0, nb_mt1, hself) + b1) ----
    #pragma unroll
    for (int j = 0; j < 4; ++j) {
        int idx = tid + j * TPB;              // 0..1023
        int node = idx >> 6, col = idx & 63;
        float m = fmaxf(fmaxf(nbpart[(node * 2) * 66 + col], nbpart[(node * 2 + 1) * 66 + col]),
                        hself[node * 66 + col]);
        aggrb[node * 66 + col] = fmaxf(m + sB[col], 0.f);
    }
    asm volatile("cp.async.wait_group 0;" ::: "memory");   // E1F/W2F arrived (per-thread)
    __syncthreads();                                       // aggrb + E1F/W2F visible to all

    // ---- MMA epilogue 1: y1 = relu(aggr @ E1^T), [16 x 64]; warp w -> n-tile w ----
    {
        float acc[4] = {0.f, 0.f, 0.f, 0.f};
        #pragma unroll
        for (int k0 = 0; k0 < 4; ++k0) {
            const int cb = 16 * k0 + 2 * tm4;
            uint32_t ah[4], al[4];
            {
                const float* ap = aggrb + t4 * 66 + cb;
                split2h(*(const float2*)ap,                ah[0], al[0]);
                split2h(*(const float2*)(ap + 8 * 66),     ah[1], al[1]);
                split2h(*(const float2*)(ap + 8),          ah[2], al[2]);
                split2h(*(const float2*)(ap + 8 * 66 + 8), ah[3], al[3]);
            }
            const float* bp = E1F + (wid * 8 + t4) * 68 + cb;
            uint32_t b0 = cvt_h2(*(const float2*)bp);
            uint32_t b1 = cvt_h2(*(const float2*)(bp + 8));
            mma16816h(acc, ah[0], ah[1], ah[2], ah[3], b0, b1);
            mma16816h(acc, al[0], al[1], al[2], al[3], b0, b1);
        }
        __syncthreads();   // nbpart fully consumed by combine; safe to overwrite as ynorm
        const int c = wid * 8 + 2 * tm4;
        *(float2*)(ynorm + t4 * 68 + c)       = make_float2(fmaxf(acc[0], 0.f), fmaxf(acc[1], 0.f));
        *(float2*)(ynorm + (t4 + 8) * 68 + c) = make_float2(fmaxf(acc[2], 0.f), fmaxf(acc[3], 0.f));
    }
    __syncthreads();

    // ---- per-node inverse L2 norm: warp w -> nodes w, w+8 ----
    {
        #pragma unroll
        for (int h = 0; h < 2; ++h) {
            const int node = wid + h * 8;
            float2 y = *(const float2*)(ynorm + node * 68 + 2 * lane);
            float s = y.x * y.x + y.y * y.y;
            #pragma unroll
            for (int off = 16; off; off >>= 1) s += __shfl_xor_sync(0xffffffffu, s, off);
            if (lane == 0) sInv[node] = (s > 0.f) ? (1.0f / sqrtf(s)) : 1.0f;
        }
    }
    __syncthreads();

    // ---- MMA epilogue 2: h2 = (y1*inv) @ W2^T + b2; max over 16 nodes -> global max ----
    {
        const float i0 = sInv[t4], i1 = sInv[t4 + 8];
        float acc[4] = {0.f, 0.f, 0.f, 0.f};
        #pragma unroll
        for (int k0 = 0; k0 < 4; ++k0) {
            const int cb = 16 * k0 + 2 * tm4;
            uint32_t ah[4], al[4];
            {
                const float* ap = ynorm + t4 * 68 + cb;
                float2 v0 = *(const float2*)ap;
                float2 v1 = *(const float2*)(ap + 8 * 68);
                float2 v2 = *(const float2*)(ap + 8);
                float2 v3 = *(const float2*)(ap + 8 * 68 + 8);
                split2h(make_float2(v0.x * i0, v0.y * i0), ah[0], al[0]);
                split2h(make_float2(v1.x * i1, v1.y * i1), ah[1], al[1]);
                split2h(make_float2(v2.x * i0, v2.y * i0), ah[2], al[2]);
                split2h(make_float2(v3.x * i1, v3.y * i1), ah[3], al[3]);
            }
            const float* bp = W2F + (wid * 8 + t4) * 68 + cb;
            uint32_t b0 = cvt_h2(*(const float2*)bp);
            uint32_t b1 = cvt_h2(*(const float2*)(bp + 8));
            mma16816h(acc, ah[0], ah[1], ah[2], ah[3], b0, b1);
            mma16816h(acc, al[0], al[1], al[2], al[3], b0, b1);
        }
        // max over 16 rows (nodes): in-reg rows t4/t4+8, then reduce over t4
        float v0 = fmaxf(acc[0], acc[2]);
        float v1 = fmaxf(acc[1], acc[3]);
        #pragma unroll
        for (int off = 4; off <= 16; off <<= 1) {
            v0 = fmaxf(v0, __shfl_xor_sync(0xffffffffu, v0, off));
            v1 = fmaxf(v1, __shfl_xor_sync(0xffffffffu, v1, off));
        }
        if (lane < 4) {
            const int c = wid * 8 + 2 * lane;
            atomicMax(&g_max_bits[c],     __float_as_int(v0 + sB2[c]));
            atomicMax(&g_max_bits[c + 1], __float_as_int(v1 + sB2[c + 1]));
        }
    }
}

// Final tiny stage: aggr2 -> emb2 (l2norm) -> regressor -> scalar out.
extern "C" __global__ void finalize_kernel(const float* __restrict__ E2,
                                           const float* __restrict__ rW1,
                                           const float* __restrict__ rb1,
                                           const float* __restrict__ rW2,
                                           const float* __restrict__ rb2,
                                           float* __restrict__ out)
{
    __shared__ float sa[64], se[64];
    __shared__ float red[2];
    const int tid = threadIdx.x;   // 64 threads

    sa[tid] = __int_as_float(g_max_bits[tid]);   // relu(max h2+b2) via 0-init floor
    __syncthreads();

    float acc = 0.f;
    const float* er = E2 + tid * 64;
    #pragma unroll 8
    for (int d = 0; d < 64; ++d) acc += er[d] * sa[d];
    acc = fmaxf(acc, 0.f);

    float s = acc * acc;
    #pragma unroll
    for (int off = 16; off; off >>= 1) s += __shfl_xor_sync(0xffffffffu, s, off);
    if ((tid & 31) == 0) red[tid >> 5] = s;
    __syncthreads();
    const float stot = red[0] + red[1];
    const float inv = (stot > 0.f) ? (1.0f / sqrtf(stot)) : 1.0f;
    se[tid] = acc * inv;
    __syncthreads();

    float h = rb1[tid];
    const float* wr = rW1 + tid * 64;
    #pragma unroll 8
    for (int d = 0; d < 64; ++d) h += wr[d] * se[d];
    h = fmaxf(h, 0.f);

    float v = h * rW2[tid];
    #pragma unroll
    for (int off = 16; off; off >>= 1) v += __shfl_xor_sync(0xffffffffu, v, off);
    if ((tid & 31) == 0) red[tid >> 5] = v;
    __syncthreads();
    if (tid == 0) out[0] = red[0] + red[1] + rb2[0];
}

// Reset accumulator for the next replay (3rd launch; keeps ncu slot on stage1).
extern "C" __global__ void reset_kernel() {
    if (threadIdx.x < 64) g_max_bits[threadIdx.x] = 0;
}

extern "C" void kernel_launch(void* const* d_in, const int* in_sizes, int n_in,
                              void* d_out, int out_size)
{
    const float* xs  = (const float*)d_in[0];
    const float* xnb = (const float*)d_in[1];
    const float* W1  = (const float*)d_in[2];
    const float* b1  = (const float*)d_in[3];
    const float* E1  = (const float*)d_in[4];
    const float* W2  = (const float*)d_in[5];
    const float* b2  = (const float*)d_in[6];
    const float* E2  = (const float*)d_in[7];
    const float* rW1 = (const float*)d_in[8];
    const float* rb1 = (const float*)d_in[9];
    const float* rW2 = (const float*)d_in[10];
    const float* rb2 = (const float*)d_in[11];

    const int n = in_sizes[0] / 64;
    const int blocks = (n + NPC - 1) / NPC;

    static int attr_done = 0;
    if (!attr_done) {
        cudaFuncSetAttribute(stage1_kernel, cudaFuncAttributeMaxDynamicSharedMemorySize, SM_TOTAL);
        attr_done = 1;
    }

    stage1_kernel<<<blocks, TPB, SM_TOTAL>>>(xs, xnb, W1, b1, E1, W2, b2, n);
    finalize_kernel<<<1, 64>>>(E2, rW1, rb1, rW2, rb2, (float*)d_out);
    reset_kernel<<<1, 64>>>();
}